// round 17
// baseline (speedup 1.0000x reference)
#include <cuda_runtime.h>
#include <cuda_bf16.h>
#include <cstdint>

// Problem constants
#define BATCH 4096
#define DIN   256
#define DOUT  256
#define NEXP  64

#define NHALF 128        // N cols per CTA (2 CTAs per expert)
#define MCH   96         // M rows per chunk
#define NTHREADS 512     // 16 warps, all do MMA
#define RCAP  192
#define NCTAS 128        // one wave; co-resident

// smem byte offsets (dynamic)
#define S_WH   0                   // W hi: [256 k][128 n] bf16, 256B rows = 64KB
#define S_WL   65536               // W lo
#define S_XH   131072              // x hi: [96 m][256 k] bf16, 512B rows = 48KB
#define S_XL   180224              // x lo
#define S_BIAS 229376              // 128 floats
#define S_ROWS 229888              // RCAP ints
#define S_CNT  230656
#define SMEM_BYTES 230912

__device__ int g_sel[BATCH];                    // decoded selector
__device__ __nv_bfloat16 g_xh[BATCH * DIN];     // x hi split (bf16), row-major
__device__ __nv_bfloat16 g_xl[BATCH * DIN];     // x lo split
__device__ int g_arrive;                        // decode barrier
__device__ int g_done;                          // end-of-kernel counter

// ---------------------------------------------------------------------------
__device__ __forceinline__ uint32_t bf2(float lo, float hi) {
    uint32_t r;
    asm("cvt.rn.bf16x2.f32 %0, %1, %2;" : "=r"(r) : "f"(hi), "f"(lo));
    return r;
}
__device__ __forceinline__ float bflo_f(uint32_t p) { return __uint_as_float(p << 16); }
__device__ __forceinline__ float bfhi_f(uint32_t p) { return __uint_as_float(p & 0xffff0000u); }

__device__ __forceinline__ uint32_t smem_to_u32(const void* p) {
    uint32_t a;
    asm("{ .reg .u64 t; cvta.to.shared.u64 t, %1; cvt.u32.u64 %0, t; }"
        : "=r"(a) : "l"(p));
    return a;
}

#define CP_ASYNC16(DST, SRC) \
    asm volatile("cp.async.cg.shared.global [%0], [%1], 16;" \
                 :: "r"(DST), "l"(SRC))
#define CP_COMMIT() asm volatile("cp.async.commit_group;")
#define CP_WAIT(N)  asm volatile("cp.async.wait_group %0;" :: "n"(N))

#define LDSM4(R, ADDR) \
    asm volatile("ldmatrix.sync.aligned.m8n8.x4.shared.b16 {%0,%1,%2,%3}, [%4];" \
        : "=r"((R)[0]), "=r"((R)[1]), "=r"((R)[2]), "=r"((R)[3]) : "r"(ADDR))

#define LDSM4T(R, ADDR) \
    asm volatile("ldmatrix.sync.aligned.m8n8.x4.trans.shared.b16 {%0,%1,%2,%3}, [%4];" \
        : "=r"((R)[0]), "=r"((R)[1]), "=r"((R)[2]), "=r"((R)[3]) : "r"(ADDR))

#define MMA16816(D, A, B0, B1) \
    asm volatile("mma.sync.aligned.m16n8k16.row.col.f32.bf16.bf16.f32 " \
        "{%0,%1,%2,%3}, {%4,%5,%6,%7}, {%8,%9}, {%0,%1,%2,%3};" \
        : "+r"((D)[0]), "+r"((D)[1]), "+r"((D)[2]), "+r"((D)[3]) \
        : "r"((A)[0]), "r"((A)[1]), "r"((A)[2]), "r"((A)[3]), "r"(B0), "r"(B1))

// convert 8 floats (v0,v1) -> bf16 hi/lo uint4 pair, store to two pointers
#define CVT_STORE(v0, v1, DSTH, DSTL) do {                                   \
    uint32_t h0 = bf2((v0).x, (v0).y), h1 = bf2((v0).z, (v0).w);             \
    uint32_t h2 = bf2((v1).x, (v1).y), h3 = bf2((v1).z, (v1).w);             \
    uint32_t l0 = bf2((v0).x - bflo_f(h0), (v0).y - bfhi_f(h0));             \
    uint32_t l1 = bf2((v0).z - bflo_f(h1), (v0).w - bfhi_f(h1));             \
    uint32_t l2 = bf2((v1).x - bflo_f(h2), (v1).y - bfhi_f(h2));             \
    uint32_t l3 = bf2((v1).z - bflo_f(h3), (v1).w - bfhi_f(h3));             \
    *(uint4*)(DSTH) = make_uint4(h0, h1, h2, h3);                            \
    *(uint4*)(DSTL) = make_uint4(l0, l1, l2, l3);                            \
} while (0)

// ---------------------------------------------------------------------------
// Single fused kernel. blockIdx.y = expert, blockIdx.x = n-half. 16 warps.
// Phase A (pre-barrier): decode own 32 onehot rows -> g_sel; convert own 32
//   x rows -> g_xh/g_xl (bf16, gmem); convert full W tile -> smem (hides spin).
// Phase B (post-barrier): compact rows; cp.async-gather bf16 x into swizzled
//   smem (4 k-tile groups); all 16 warps run 48x16-warp-tile HMMA per tile.
// 3-term bf16 split in fp32: xh*Wh + xh*Wl + xl*Wh.
// ---------------------------------------------------------------------------
__global__ void __launch_bounds__(NTHREADS, 1)
gemm_kernel(const float* __restrict__ x,
            const float* __restrict__ onehot,
            const float* __restrict__ W,
            const float* __restrict__ Bw,
            float* __restrict__ out) {
    extern __shared__ char smem[];
    const uint32_t sb = smem_to_u32(smem);
    float* s_bias = (float*)(smem + S_BIAS);
    int*   s_rows = (int*)(smem + S_ROWS);
    int*   s_cnt  = (int*)(smem + S_CNT);

    const int tid  = threadIdx.x;
    const int lane = tid & 31;
    const int wid  = tid >> 5;
    const int e    = blockIdx.y;
    const int n0   = blockIdx.x * NHALF;
    const int cid  = blockIdx.y * gridDim.x + blockIdx.x;   // 0..127

    if (tid == 0) *s_cnt = 0;

    // --- decode this CTA's 32-row slab of onehot (coalesced, 1 granule/thread) ---
    {
        const float4* slab = (const float4*)(onehot + ((size_t)cid << 11));
        int r  = tid >> 4;             // row within slab (0..31)
        int c4 = (tid & 15) << 2;      // expert base of this quad
        float4 v = slab[tid];
        int sel = -1;
        if (v.x > 0.5f) sel = c4 + 0;
        if (v.y > 0.5f) sel = c4 + 1;
        if (v.z > 0.5f) sel = c4 + 2;
        if (v.w > 0.5f) sel = c4 + 3;
        if (sel >= 0) g_sel[cid * 32 + r] = sel;
    }

    // --- convert this CTA's 32 x rows to bf16 hi/lo in gmem (coalesced) ---
    {
        const float4* xs = (const float4*)(x + ((size_t)cid << 13));  // 32 rows
        uint4* xh = (uint4*)g_xh + ((size_t)cid << 10);   // 1024 granules/slab
        uint4* xl = (uint4*)g_xl + ((size_t)cid << 10);
#pragma unroll
        for (int j = 0; j < 2; j++) {
            int u = tid + 512 * j;        // granule 0..1023 (8 floats each)
            float4 v0 = xs[2 * u];
            float4 v1 = xs[2 * u + 1];
            CVT_STORE(v0, v1, xh + u, xl + u);
        }
    }
    if (tid < NHALF) s_bias[tid] = Bw[(e << 8) + n0 + tid];

    __threadfence();       // publish g_sel + g_xh/g_xl
    __syncthreads();
    if (tid == 0) atomicAdd(&g_arrive, 1);

    // --- convert full W tile [256k][128n] -> smem bf16 hi/lo (hides barrier) ---
    {
        const float* We = W + ((size_t)e << 16) + n0;
#pragma unroll
        for (int it = 0; it < 8; it++) {
            int u  = tid + 512 * it;    // 0..4095 granules
            int k  = u >> 4;
            int nc = u & 15;
            const float* src = We + ((size_t)k << 8) + (nc << 3);
            float4 v0 = *(const float4*)(src);
            float4 v1 = *(const float4*)(src + 4);
            uint32_t gsw = (uint32_t)((nc & 8) | ((nc & 7) ^ (k & 7)));
            uint32_t dst = ((uint32_t)k << 8) + (gsw << 4);
            CVT_STORE(v0, v1, smem + S_WH + dst, smem + S_WL + dst);
        }
    }

    // --- global barrier: all CTAs decoded + converted x ---
    if (tid == 0) {
        while (*(volatile int*)&g_arrive < NCTAS) { __nanosleep(64); }
    }
    __syncthreads();
    __threadfence();   // acquire g_sel / g_xh / g_xl

    // --- compact this expert's rows ---
    {
        int4 sv[2];
#pragma unroll
        for (int j = 0; j < 2; j++)
            sv[j] = ((const int4*)g_sel)[tid + 512 * j];
#pragma unroll
        for (int j = 0; j < 2; j++) {
            int rb = (tid + 512 * j) << 2;
            if (sv[j].x == e) { int p = atomicAdd(s_cnt, 1); if (p < RCAP) s_rows[p] = rb + 0; }
            if (sv[j].y == e) { int p = atomicAdd(s_cnt, 1); if (p < RCAP) s_rows[p] = rb + 1; }
            if (sv[j].z == e) { int p = atomicAdd(s_cnt, 1); if (p < RCAP) s_rows[p] = rb + 2; }
            if (sv[j].w == e) { int p = atomicAdd(s_cnt, 1); if (p < RCAP) s_rows[p] = rb + 3; }
        }
    }
    __syncthreads();
    const int cnt = min(*s_cnt, RCAP);

    // warp/lane geometry: warp grid 2m x 8n, warp tile 48m x 16n (all 16 warps)
    const int mw0 = (wid >> 3) * 48;
    const int nw0 = (wid & 7) * 16;
    const int lm    = lane & 15;
    const int lhalf = lane >> 4;
    const int l7    = lane & 7;

    uint32_t aBaseH[3], aBaseL[3];
#pragma unroll
    for (int i = 0; i < 3; i++) {
        uint32_t roff = (uint32_t)(mw0 + 16 * i + lm) << 9;
        aBaseH[i] = sb + S_XH + roff;
        aBaseL[i] = sb + S_XL + roff;
    }
    const int ncA = (wid & 7) * 2 + lhalf;
    const uint32_t gswBA = (uint32_t)((ncA & 8) | ((ncA & 7) ^ l7)) << 4;
    const uint32_t bBaseH = sb + S_WH + ((uint32_t)lm << 8) + gswBA;
    const uint32_t bBaseL = sb + S_WL + ((uint32_t)lm << 8) + gswBA;

    int m0 = 0;
    while (true) {
        const int nrows = min(MCH, cnt - m0);

        // --- issue cp.async gather of bf16 x: 4 k-tile groups ---
#pragma unroll
        for (int t = 0; t < 4; t++) {
#pragma unroll
            for (int j = 0; j < 2; j++) {
                int u = tid + 512 * j;          // 0..1023; use first 768
                if (u < 768) {
                    int r = u >> 3;             // 0..95
                    int c = 8 * t + (u & 7);    // granule 0..31
                    if (r < nrows) {
                        size_t so = (((size_t)s_rows[m0 + r]) << 9) + ((size_t)c << 4);
                        uint32_t gsw = (uint32_t)((c & 24) | ((c & 7) ^ (r & 7)));
                        uint32_t doff = ((uint32_t)r << 9) + (gsw << 4);
                        CP_ASYNC16(sb + S_XH + doff, (const char*)g_xh + so);
                        CP_ASYNC16(sb + S_XL + doff, (const char*)g_xl + so);
                    }
                }
            }
            CP_COMMIT();
        }

        // --- mma mainloop: per tile wait + 4 ks; D[3 m][2 n] fp32 ---
        uint32_t d[3][2][4];
#pragma unroll
        for (int i = 0; i < 3; i++)
#pragma unroll
            for (int j = 0; j < 2; j++)
#pragma unroll
                for (int q = 0; q < 4; q++) d[i][j][q] = 0u;

#pragma unroll 1
        for (int t = 0; t < 4; t++) {
            switch (t) {
                case 0: CP_WAIT(3); break;
                case 1: CP_WAIT(2); break;
                case 2: CP_WAIT(1); break;
                default: CP_WAIT(0); break;
            }
            __syncthreads();   // all threads' group-t data visible to all warps

#pragma unroll
            for (int kk = 0; kk < 4; kk++) {
                int ks = 4 * t + kk;
                int gA = 2 * ks + lhalf;
                uint32_t swA = (uint32_t)((gA & 24) | ((gA & 7) ^ l7)) << 4;
                uint32_t bK = (uint32_t)ks << 12;

                uint32_t ah[3][4], al[3][4];
#pragma unroll
                for (int i = 0; i < 3; i++) {
                    LDSM4(ah[i], aBaseH[i] + swA);
                    LDSM4(al[i], aBaseL[i] + swA);
                }
                uint32_t bh[4], bl[4];
                LDSM4T(bh, bBaseH + bK);
                LDSM4T(bl, bBaseL + bK);

#pragma unroll
                for (int i = 0; i < 3; i++)
#pragma unroll
                    for (int j = 0; j < 2; j++) {
                        MMA16816(d[i][j], ah[i], bh[2 * j], bh[2 * j + 1]);
                        MMA16816(d[i][j], ah[i], bl[2 * j], bl[2 * j + 1]);
                        MMA16816(d[i][j], al[i], bh[2 * j], bh[2 * j + 1]);
                    }
            }
        }

        // --- epilogue: add bias, scatter rows ---
#pragma unroll
        for (int i = 0; i < 3; i++) {
            int rlo = mw0 + 16 * i + (lane >> 2);
#pragma unroll
            for (int half = 0; half < 2; half++) {
                int m = m0 + rlo + 8 * half;
                if (m < cnt) {
                    float* op = out + ((size_t)s_rows[m] << 8) + n0;
#pragma unroll
                    for (int j = 0; j < 2; j++) {
                        int c = nw0 + 8 * j + 2 * (lane & 3);
                        float2 b = *(float2*)(s_bias + c);
                        float2 v;
                        v.x = __uint_as_float(d[i][j][2 * half + 0]) + b.x;
                        v.y = __uint_as_float(d[i][j][2 * half + 1]) + b.y;
                        *(float2*)(op + c) = v;
                    }
                }
            }
        }

        m0 += MCH;
        if (m0 >= cnt) break;
        __syncthreads();   // all warps done reading s_x before restage
    }

    // --- reset counters for next graph replay ---
    __syncthreads();
    if (tid == 0) {
        __threadfence();
        int od = atomicAdd(&g_done, 1);
        if (od == NCTAS - 1) {
            g_arrive = 0;
            g_done = 0;
            __threadfence();
        }
    }
}

// ---------------------------------------------------------------------------
extern "C" void kernel_launch(void* const* d_in, const int* in_sizes, int n_in,
                              void* d_out, int out_size) {
    const float* x      = (const float*)d_in[0];
    const float* onehot = (const float*)d_in[1];
    const float* W      = (const float*)d_in[2];
    const float* Bw     = (const float*)d_in[3];
    float* out          = (float*)d_out;

    cudaFuncSetAttribute(gemm_kernel,
                         cudaFuncAttributeMaxDynamicSharedMemorySize,
                         SMEM_BYTES);

    gemm_kernel<<<dim3(DOUT / NHALF, NEXP), NTHREADS, SMEM_BYTES>>>(
        x, onehot, W, Bw, out);
}